// round 16
// baseline (speedup 1.0000x reference)
#include <cuda_runtime.h>
#include <cstdint>

// Problem constants
#define BB   16
#define CC   128
#define C4C  32
#define NPIX 2304                      // H*W = 48*48
#define NT   18                        // NPIX / 128
#define BN_EPS 1e-5f

// -------- scratch (device globals; no allocation allowed) --------
__device__ uint16_t g_Kh   [BB * C4C * NPIX];        // bf16 K [b][k][n]
__device__ uint16_t g_QTh  [BB * NPIX * C4C];        // bf16 QT [b][m][k]
__device__ uint16_t g_Vh   [BB * CC  * NPIX];        // bf16 V [b][c][m]
__device__ uint16_t g_Wvh  [CC * CC];                // bf16 (w_v * bn_scale)
__device__ float    g_Wredt[CC * 2 * CC];            // tf32-RNE w_red
__device__ float    g_Xr   [BB * 2 * CC * NPIX];     // tf32-RNE x_cat (38 MB)
__device__ float    g_pZ   [BB * NT];
__device__ int      g_mk   [BB];                     // atomicMax accum (||K||^2)
__device__ int      g_mq   [BB];                     // atomicMax accum (||Q||^2)

// -------- packed f32x2 helpers --------
__device__ __forceinline__ unsigned long long pk2(float lo, float hi) {
    unsigned long long r;
    asm("mov.b64 %0, {%1,%2};" : "=l"(r) : "f"(lo), "f"(hi));
    return r;
}
__device__ __forceinline__ float2 up2(unsigned long long v) {
    float2 r;
    asm("mov.b64 {%0,%1}, %2;" : "=f"(r.x), "=f"(r.y) : "l"(v));
    return r;
}
__device__ __forceinline__ void fma2(unsigned long long& d,
                                     unsigned long long a,
                                     unsigned long long b) {
    asm("fma.rn.f32x2 %0, %1, %2, %0;" : "+l"(d) : "l"(a), "l"(b));
}
__device__ __forceinline__ uint32_t smem_to_u32(const void* p) {
    uint32_t a;
    asm("{ .reg .u64 t; cvta.to.shared.u64 t, %1; cvt.u32.u64 %0, t; }"
        : "=r"(a) : "l"(p));
    return a;
}
__device__ __forceinline__ void cp16(uint32_t dst, const void* src) {
    asm volatile("cp.async.cg.shared.global [%0], [%1], 16;"
                 :: "r"(dst), "l"(src) : "memory");
}
#define CP_COMMIT() asm volatile("cp.async.commit_group;" ::: "memory")
#define CP_WAIT0()  asm volatile("cp.async.wait_group 0;" ::: "memory")

// pack two f32 -> bf16x2 (lo = p0, hi = p1)
__device__ __forceinline__ uint32_t bfpack(float p0, float p1) {
    uint32_t u;
    asm("cvt.rn.bf16x2.f32 %0, %1, %2;" : "=r"(u) : "f"(p1), "f"(p0));
    return u;
}
__device__ __forceinline__ float bflo(uint32_t u) {
    return __uint_as_float(u << 16);
}
__device__ __forceinline__ float bfhi(uint32_t u) {
    return __uint_as_float(u & 0xFFFF0000u);
}
__device__ __forceinline__ float tf32r(float x) {   // RNE round to tf32
    uint32_t u;
    asm("cvt.rna.tf32.f32 %0, %1;" : "=r"(u) : "f"(x));
    return __uint_as_float(u);
}

// -------- mma.sync + ldmatrix (family-portable, sm_80+) --------
__device__ __forceinline__ void ldsm_x4(uint32_t* r, uint32_t a) {
    asm volatile("ldmatrix.sync.aligned.m8n8.x4.shared.b16 {%0,%1,%2,%3}, [%4];"
        : "=r"(r[0]), "=r"(r[1]), "=r"(r[2]), "=r"(r[3]) : "r"(a));
}
__device__ __forceinline__ void ldsm_x2t(uint32_t* r, uint32_t a) {
    asm volatile("ldmatrix.sync.aligned.m8n8.x2.trans.shared.b16 {%0,%1}, [%2];"
        : "=r"(r[0]), "=r"(r[1]) : "r"(a));
}
__device__ __forceinline__ void mma_bf16(float* d, const uint32_t* a,
                                         const uint32_t* b) {
    asm volatile(
        "mma.sync.aligned.m16n8k16.row.col.f32.bf16.bf16.f32 "
        "{%0,%1,%2,%3},{%4,%5,%6,%7},{%8,%9},{%0,%1,%2,%3};"
        : "+f"(d[0]), "+f"(d[1]), "+f"(d[2]), "+f"(d[3])
        : "r"(a[0]), "r"(a[1]), "r"(a[2]), "r"(a[3]), "r"(b[0]), "r"(b[1]));
}
__device__ __forceinline__ void mma_tf32(float* d, const uint32_t* a,
                                         const uint32_t* b) {
    asm volatile(
        "mma.sync.aligned.m16n8k8.row.col.f32.tf32.tf32.f32 "
        "{%0,%1,%2,%3},{%4,%5,%6,%7},{%8,%9},{%0,%1,%2,%3};"
        : "+f"(d[0]), "+f"(d[1]), "+f"(d[2]), "+f"(d[3])
        : "r"(a[0]), "r"(a[1]), "r"(a[2]), "r"(a[3]), "r"(b[0]), "r"(b[1]));
}

// ============================================================================
// prep (merged): Wvh bf16 + Wredt tf32 RNE + zero norm accums + Xr = rne(x_cat)
// grid 2048 x 256, grid-stride over X.
// ============================================================================
__global__ void __launch_bounds__(256) prep_kernel(
    const float* __restrict__ Wv,
    const float* __restrict__ v_g, const float* __restrict__ v_v,
    const float* __restrict__ Wred,
    const float* __restrict__ X)
{
    int i = blockIdx.x * 256 + threadIdx.x;
    if (i < BB) { g_mk[i] = 0; g_mq[i] = 0; }
    if (i < CC * CC) {
        int o = i >> 7;
        float s = v_g[o] * rsqrtf(v_v[o] + BN_EPS);
        g_Wvh[i] = (uint16_t)(bfpack(Wv[i] * s, 0.f) & 0xFFFF);
    }
    if (i < CC * 2 * CC) g_Wredt[i] = tf32r(Wred[i]);

    const size_t total4 = (size_t)BB * 2 * CC * NPIX / 4;
    const size_t stride = (size_t)gridDim.x * 256;
    for (size_t j = (size_t)blockIdx.x * 256 + threadIdx.x; j < total4; j += stride) {
        float4 v = ((const float4*)X)[j];
        v.x = tf32r(v.x); v.y = tf32r(v.y);
        v.z = tf32r(v.z); v.w = tf32r(v.w);
        ((float4*)g_Xr)[j] = v;
    }
}

// ============================================================================
// norm (parallel): grid (NT, B), 128 thr; atomicMax partial maxima.
// ============================================================================
__global__ void __launch_bounds__(128) norm_kernel()
{
    __shared__ float r1[128], r2[128];
    const int t  = threadIdx.x;
    const int b  = blockIdx.y;
    const int n  = blockIdx.x * 128 + t;
    const uint16_t* Kb  = g_Kh  + (size_t)b * C4C * NPIX;
    const uint16_t* QTb = g_QTh + (size_t)b * NPIX * C4C;

    float sk = 0.f;
#pragma unroll
    for (int k = 0; k < C4C; k++) {
        float vk = bflo((uint32_t)Kb[(size_t)k * NPIX + n]);
        sk += vk * vk;
    }
    float sq = 0.f;
    const uint32_t* qr = (const uint32_t*)(QTb + (size_t)n * C4C);
#pragma unroll
    for (int j = 0; j < 16; j++) {
        uint32_t u = qr[j];
        float lo = bflo(u), hi = bfhi(u);
        sq += lo * lo + hi * hi;
    }
    r1[t] = sk; r2[t] = sq;
    __syncthreads();
    for (int s = 64; s > 0; s >>= 1) {
        if (t < s) { r1[t] = fmaxf(r1[t], r1[t + s]); r2[t] = fmaxf(r2[t], r2[t + s]); }
        __syncthreads();
    }
    if (t == 0) {
        atomicMax(&g_mk[b], __float_as_int(r1[0]));
        atomicMax(&g_mq[b], __float_as_int(r2[0]));
    }
}

// ============================================================================
// convfused (R15 verbatim): phase 1 tf32 mma (pre-rounded operands);
// phase 2 bf16 mma V-conv.
// ============================================================================
#define CF_XS_OFF   36864
#define CF_WVH_OFF  34816
#define CF_SMEM_BYTES 70656

__global__ void __launch_bounds__(256, 2) convfused_kernel(
    const float* __restrict__ gam, const float* __restrict__ bet,
    const float* __restrict__ mean, const float* __restrict__ var,
    const float* __restrict__ v_g, const float* __restrict__ v_b,
    const float* __restrict__ v_m, const float* __restrict__ v_v,
    float* __restrict__ out)
{
    extern __shared__ __align__(16) char csm[];
    __shared__ float scale_s[128], bias_s[128], biasv_s[128];

    const int t  = threadIdx.x;
    const int b  = blockIdx.y;
    const int n0 = blockIdx.x * 128;
    const int CIN = 2 * CC;
    const int lane = t & 31, wid = t >> 5;
    const int wr = wid >> 2, wn = wid & 3;
    const int g = lane >> 2, t2 = lane & 3;

    if (t < 128) {
        float s = gam[t] * rsqrtf(var[t] + BN_EPS);
        scale_s[t] = s;
        bias_s[t]  = bet[t] - mean[t] * s;
        float sv = v_g[t] * rsqrtf(v_v[t] + BN_EPS);
        biasv_s[t] = v_b[t] - v_m[t] * sv;
    }

    const float* Xb = g_Xr + (size_t)b * CIN * NPIX + n0;
    const uint32_t sb = smem_to_u32(csm);
    float* Wsf = (float*)csm;                       // [2][128][36]
    float* Xsf = (float*)(csm + CF_XS_OFF);         // [2][32][132]

    auto load_chunk = [&](int c0, int buf) {
        {
            int o = t >> 1, h = t & 1;
            uint32_t dst = sb + (uint32_t)(buf * 128 * 36 + o * 36 + h * 16) * 4;
            const float* src = g_Wredt + (size_t)o * CIN + c0 + h * 16;
            cp16(dst, src);      cp16(dst + 16, src + 4);
            cp16(dst + 32, src + 8); cp16(dst + 48, src + 12);
        }
        {
            int k = t >> 3, seg = t & 7;
            uint32_t dst = sb + CF_XS_OFF
                         + (uint32_t)(buf * 32 * 132 + k * 132 + seg * 16) * 4;
            const float* src = Xb + (size_t)(c0 + k) * NPIX + seg * 16;
            cp16(dst, src);      cp16(dst + 16, src + 4);
            cp16(dst + 32, src + 8); cp16(dst + 48, src + 12);
        }
    };

    load_chunk(0, 0);
    CP_COMMIT();

    float acc[4][4][4];
#pragma unroll
    for (int ct = 0; ct < 4; ct++)
#pragma unroll
        for (int nt = 0; nt < 4; nt++)
#pragma unroll
            for (int j = 0; j < 4; j++) acc[ct][nt][j] = 0.f;

    for (int ch = 0; ch < 8; ch++) {
        const int buf = ch & 1;
        CP_WAIT0();
        __syncthreads();
        if (ch + 1 < 8) { load_chunk((ch + 1) << 5, buf ^ 1); CP_COMMIT(); }

        const float* Wb2 = Wsf + buf * 128 * 36;
        const float* Xb2 = Xsf + buf * 32 * 132;
#pragma unroll
        for (int ks = 0; ks < 4; ks++) {
            const int k0 = ks * 8;
            uint32_t A[4][4];
#pragma unroll
            for (int ct = 0; ct < 4; ct++) {
                int r0 = wr * 64 + ct * 16 + g;
                A[ct][0] = __float_as_uint(Wb2[r0 * 36 + k0 + t2]);
                A[ct][1] = __float_as_uint(Wb2[(r0 + 8) * 36 + k0 + t2]);
                A[ct][2] = __float_as_uint(Wb2[r0 * 36 + k0 + 4 + t2]);
                A[ct][3] = __float_as_uint(Wb2[(r0 + 8) * 36 + k0 + 4 + t2]);
            }
            uint32_t Bf[4][2];
#pragma unroll
            for (int nt = 0; nt < 4; nt++) {
                int col = wn * 32 + nt * 8 + g;
                Bf[nt][0] = __float_as_uint(Xb2[(k0 + t2) * 132 + col]);
                Bf[nt][1] = __float_as_uint(Xb2[(k0 + 4 + t2) * 132 + col]);
            }
#pragma unroll
            for (int ct = 0; ct < 4; ct++)
#pragma unroll
                for (int nt = 0; nt < 4; nt++)
                    mma_tf32(acc[ct][nt], A[ct], Bf[nt]);
        }
        __syncthreads();
    }
    __syncthreads();

    {
        int o = t >> 1, h = t & 1;
        uint32_t dst = sb + CF_WVH_OFF + (uint32_t)(o * 136 + h * 64) * 2;
        const uint16_t* src = g_Wvh + (size_t)o * CC + h * 64;
#pragma unroll
        for (int q = 0; q < 8; q++) cp16(dst + q * 16, src + q * 8);
    }
    CP_COMMIT();

    {
        uint16_t* xh = (uint16_t*)csm;              // [128][136]
        float* Yb = out + (size_t)b * (2 * CC) * NPIX + n0;
#pragma unroll
        for (int ct = 0; ct < 4; ct++) {
            int row = wr * 64 + ct * 16 + g;
            float s0 = scale_s[row],     b0 = bias_s[row];
            float s1 = scale_s[row + 8], b1 = bias_s[row + 8];
#pragma unroll
            for (int nt = 0; nt < 4; nt++) {
                int col = wn * 32 + nt * 8 + 2 * t2;
                float r0 = fmaxf(acc[ct][nt][0] * s0 + b0, 0.f);
                float r1 = fmaxf(acc[ct][nt][1] * s0 + b0, 0.f);
                float r2 = fmaxf(acc[ct][nt][2] * s1 + b1, 0.f);
                float r3 = fmaxf(acc[ct][nt][3] * s1 + b1, 0.f);
                *(float2*)&Yb[(size_t)row * NPIX + col]       = make_float2(r0, r1);
                *(float2*)&Yb[(size_t)(row + 8) * NPIX + col] = make_float2(r2, r3);
                *(uint32_t*)&xh[row * 136 + col]       = bfpack(r0, r1);
                *(uint32_t*)&xh[(row + 8) * 136 + col] = bfpack(r2, r3);
            }
        }
    }
    CP_WAIT0();
    __syncthreads();

    const int arow = wr * 64 + ((lane >> 3) & 1) * 8 + (lane & 7);
    const int acol = (lane >> 4) * 8;
    const uint32_t aBase = sb + CF_WVH_OFF + (uint32_t)(arow * 136 + acol) * 2;
    const int l16 = lane & 15;
    const uint32_t bBase = sb + (uint32_t)(l16 * 136 + wn * 32) * 2;

    float vac[4][4][4];
#pragma unroll
    for (int ct = 0; ct < 4; ct++)
#pragma unroll
        for (int nt = 0; nt < 4; nt++)
#pragma unroll
            for (int j = 0; j < 4; j++) vac[ct][nt][j] = 0.f;

#pragma unroll
    for (int kk = 0; kk < 8; kk++) {
        uint32_t A2[4][4];
#pragma unroll
        for (int ct = 0; ct < 4; ct++)
            ldsm_x4(A2[ct], aBase + (uint32_t)(ct * 16 * 136) * 2 + kk * 32);
        uint32_t B2[4][2];
#pragma unroll
        for (int nt = 0; nt < 4; nt++)
            ldsm_x2t(B2[nt], bBase + (uint32_t)(kk * 16 * 136) * 2 + nt * 16);
#pragma unroll
        for (int ct = 0; ct < 4; ct++)
#pragma unroll
            for (int nt = 0; nt < 4; nt++)
                mma_bf16(vac[ct][nt], A2[ct], B2[nt]);
    }

    uint16_t* Vb = g_Vh + (size_t)b * CC * NPIX + n0;
#pragma unroll
    for (int ct = 0; ct < 4; ct++) {
        int row = wr * 64 + ct * 16 + g;
        float b0 = biasv_s[row], b1 = biasv_s[row + 8];
#pragma unroll
        for (int nt = 0; nt < 4; nt++) {
            int col = wn * 32 + nt * 8 + 2 * t2;
            *(uint32_t*)&Vb[(size_t)row * NPIX + col] =
                bfpack(fmaxf(vac[ct][nt][0] + b0, 0.f),
                       fmaxf(vac[ct][nt][1] + b0, 0.f));
            *(uint32_t*)&Vb[(size_t)(row + 8) * NPIX + col] =
                bfpack(fmaxf(vac[ct][nt][2] + b1, 0.f),
                       fmaxf(vac[ct][nt][3] + b1, 0.f));
        }
    }
}

// ============================================================================
// conv_kq (verbatim): z=0 -> Kh bf16 [b][k][n] ; z=1 -> QTh bf16 [b][m][k]
// ============================================================================
__global__ void __launch_bounds__(256, 2) conv_kq_kernel(
    const float* __restrict__ Xen, const float* __restrict__ Xde,
    const float* __restrict__ W,
    const float* __restrict__ gam, const float* __restrict__ bet,
    const float* __restrict__ mean, const float* __restrict__ var)
{
    __shared__ __align__(16) float Ws[2][32 * 20];
    __shared__ __align__(16) float Xs[2][16 * 132];
    __shared__ float scale_s[32], bias_s[32];

    const int t  = threadIdx.x;
    const int b  = blockIdx.y;
    const int n0 = blockIdx.x * 128;
    const int ty = t >> 4, tx = t & 15;
    const float* X = (blockIdx.z == 0) ? Xen : Xde;

    if (t < 32) {
        float s = gam[t] * rsqrtf(var[t] + BN_EPS);
        scale_s[t] = s;
        bias_s[t]  = bet[t] - mean[t] * s;
    }

    const float* Xb = X + (size_t)b * CC * NPIX + n0;
    const uint32_t sW = smem_to_u32(Ws), sX = smem_to_u32(Xs);

    auto load_chunk = [&](int c0, int buf) {
        if (t < 128) {
            int o = t >> 2, q = t & 3;
            cp16(sW + (uint32_t)(buf * 32 * 20 + o * 20 + q * 4) * 4,
                 W + (size_t)o * CC + c0 + q * 4);
        }
        {
            int k = t >> 4, seg = t & 15;
            uint32_t dst = sX + (uint32_t)(buf * 16 * 132 + k * 132 + seg * 8) * 4;
            const float* src = Xb + (size_t)(c0 + k) * NPIX + seg * 8;
            cp16(dst, src); cp16(dst + 16, src + 4);
        }
    };

    load_chunk(0, 0);
    CP_COMMIT();

    unsigned long long acc[2][4];
#pragma unroll
    for (int i = 0; i < 2; i++)
#pragma unroll
        for (int j = 0; j < 4; j++) acc[i][j] = 0ull;

    for (int ch = 0; ch < 8; ch++) {
        const int buf = ch & 1;
        CP_WAIT0();
        __syncthreads();
        if (ch + 1 < 8) { load_chunk((ch + 1) << 4, buf ^ 1); CP_COMMIT(); }

        const float* Wb2 = Ws[buf];
        const float* Xb2 = Xs[buf];
#pragma unroll
        for (int k4 = 0; k4 < 4; k4++) {
            unsigned long long bx[4][4];
#pragma unroll
            for (int kk = 0; kk < 4; kk++)
#pragma unroll
                for (int j = 0; j < 4; j++)
                    bx[kk][j] = *(const unsigned long long*)
                        &Xb2[(k4 * 4 + kk) * 132 + 2 * tx + 32 * j];
#pragma unroll
            for (int i = 0; i < 2; i++) {
                float4 w4 = *(const float4*)&Wb2[(ty * 2 + i) * 20 + k4 * 4];
                unsigned long long d0 = pk2(w4.x, w4.x);
                unsigned long long d1 = pk2(w4.y, w4.y);
                unsigned long long d2 = pk2(w4.z, w4.z);
                unsigned long long d3 = pk2(w4.w, w4.w);
#pragma unroll
                for (int j = 0; j < 4; j++) {
                    fma2(acc[i][j], d0, bx[0][j]);
                    fma2(acc[i][j], d1, bx[1][j]);
                    fma2(acc[i][j], d2, bx[2][j]);
                    fma2(acc[i][j], d3, bx[3][j]);
                }
            }
        }
        __syncthreads();
    }

    if (blockIdx.z == 0) {
        uint16_t* Yb = g_Kh + (size_t)b * C4C * NPIX + n0 + 2 * tx;
#pragma unroll
        for (int i = 0; i < 2; i++) {
            int o = ty * 2 + i;
            float s = scale_s[o], bi = bias_s[o];
#pragma unroll
            for (int j = 0; j < 4; j++) {
                float2 p = up2(acc[i][j]);
                *(uint32_t*)&Yb[(size_t)o * NPIX + 32 * j] =
                    bfpack(fmaxf(p.x * s + bi, 0.f), fmaxf(p.y * s + bi, 0.f));
            }
        }
    } else {
        uint16_t* Yb = g_QTh + (size_t)b * NPIX * C4C;
#pragma unroll
        for (int i = 0; i < 2; i++) {
            int o = ty * 2 + i;
            float s = scale_s[o], bi = bias_s[o];
#pragma unroll
            for (int j = 0; j < 4; j++) {
                float2 p = up2(acc[i][j]);
                int n = n0 + 2 * tx + 32 * j;
                Yb[(size_t)n * C4C + o] =
                    (uint16_t)(bfpack(fmaxf(p.x * s + bi, 0.f), 0.f) & 0xFFFF);
                Yb[(size_t)(n + 1) * C4C + o] =
                    (uint16_t)(bfpack(fmaxf(p.y * s + bi, 0.f), 0.f) & 0xFFFF);
            }
        }
    }
}

// ============================================================================
// fused attention: all-bf16 tensor path. GEMM1 split by m2-half to cut live
// registers (d2[4][4] instead of d1[2][4][4]) and overlap exp with mma.
// ============================================================================
#define FS_QT_OFF  8704
#define FS_VH_OFF  18944
#define FS_PS_OFF  55808
#define FS_QT_BSZ  5120
#define FS_VH_BSZ  18432
#define FS_SMEM_BYTES 73216

__global__ void __launch_bounds__(256, 2) fused_kernel(float* __restrict__ out)
{
    extern __shared__ __align__(16) char fsm[];
    __shared__ float zred[256];

    const int t  = threadIdx.x;
    const int b  = blockIdx.y;
    const int n0 = blockIdx.x * 128;
    const int lane = t & 31, wid = t >> 5;
    const int g = lane >> 2, t2 = lane & 3;
    const int wr = wid >> 2, wn = wid & 3;
    const float Mb = sqrtf(__int_as_float(g_mk[b])) * sqrtf(__int_as_float(g_mq[b]));

    const uint32_t sb = smem_to_u32(fsm);
    const uint16_t* Kg  = g_Kh  + (size_t)b * C4C * NPIX + n0;
    const uint16_t* QTg = g_QTh + (size_t)b * NPIX * C4C;
    const uint16_t* Vg  = g_Vh  + (size_t)b * CC * NPIX;

    {
        int k = t >> 3, seg = t & 7;
        uint32_t dst = sb + (uint32_t)(k * 136 + seg * 16) * 2;
        const uint16_t* src = Kg + (size_t)k * NPIX + seg * 16;
        cp16(dst, src); cp16(dst + 16, src + 8);
    }
    auto load_chunk = [&](int m0, int buf) {
        {
            int m = t >> 2, sg = t & 3;
            uint32_t dst = sb + FS_QT_OFF + (uint32_t)buf * FS_QT_BSZ
                         + (uint32_t)(m * 40 + sg * 8) * 2;
            const uint16_t* src = QTg + (size_t)(m0 + m) * C4C + sg * 8;
            cp16(dst, src);
        }
        {
            int c = t >> 1, h = t & 1;
            uint32_t dst = sb + FS_VH_OFF + (uint32_t)buf * FS_VH_BSZ
                         + (uint32_t)(c * 72 + h * 32) * 2;
            const uint16_t* src = Vg + (size_t)c * NPIX + m0 + h * 32;
            cp16(dst, src);      cp16(dst + 16, src + 8);
            cp16(dst + 32, src + 16); cp16(dst + 48, src + 24);
        }
    };
    load_chunk(0, 0);
    CP_COMMIT();

    const int lrow = ((lane >> 3) & 1) * 8 + (lane & 7);
    const int l16  = lane & 15;
    const uint32_t aQ0 = sb + FS_QT_OFF
        + (uint32_t)((wr * 32 + lrow) * 40 + (lane >> 4) * 8) * 2;
    const uint32_t bK0 = sb + (uint32_t)(l16 * 136 + wn * 32) * 2;
    const uint32_t aV0 = sb + FS_VH_OFF
        + (uint32_t)((wr * 64 + lrow) * 72 + (lane >> 4) * 8) * 2;
    const uint32_t bP0 = sb + FS_PS_OFF + (uint32_t)(l16 * 136 + wn * 32) * 2;

    float acc[4][4][4];
#pragma unroll
    for (int ct = 0; ct < 4; ct++)
#pragma unroll
        for (int nt = 0; nt < 4; nt++)
#pragma unroll
            for (int j = 0; j < 4; j++) acc[ct][nt][j] = 0.f;
    float zacc = 0.f;

    for (int ch = 0; ch < 36; ch++) {
        const int buf = ch & 1;
        CP_WAIT0();
        __syncthreads();
        if (ch + 1 < 36) { load_chunk((ch + 1) * 64, buf ^ 1); CP_COMMIT(); }

        // ---- GEMM1 (bf16), split by m2-half: 16 live logit regs ----
        const uint32_t aQ = aQ0 + (uint32_t)buf * FS_QT_BSZ;
#pragma unroll
        for (int m2 = 0; m2 < 2; m2++) {
            float d2[4][4];
#pragma unroll
            for (int j = 0; j < 4; j++)
#pragma unroll
                for (int q = 0; q < 4; q++) d2[j][q] = 0.f;

#pragma unroll
            for (int kk = 0; kk < 2; kk++) {
                uint32_t A[4];
                ldsm_x4(A, aQ + (uint32_t)(m2 * 16 * 40) * 2 + kk * 32);
                uint32_t Bf[4][2];
#pragma unroll
                for (int nt = 0; nt < 4; nt++)
                    ldsm_x2t(Bf[nt], bK0 + (uint32_t)(kk * 16 * 136) * 2 + nt * 16);
#pragma unroll
                for (int nt = 0; nt < 4; nt++)
                    mma_bf16(d2[nt], A, Bf[nt]);
            }

            // exp + Z + bf16 store to Psm for this half
            int mrow = wr * 32 + m2 * 16 + g;
#pragma unroll
            for (int nt = 0; nt < 4; nt++) {
                int ncol = wn * 32 + nt * 8 + 2 * t2;
                float e0 = __expf(d2[nt][0] - Mb);
                float e1 = __expf(d2[nt][1] - Mb);
                float e2 = __expf(d2[nt][2] - Mb);
                float e3 = __expf(d2[nt][3] - Mb);
                zacc += (e0 + e1) + (e2 + e3);
                *(uint32_t*)(fsm + FS_PS_OFF + (size_t)(mrow * 136 + ncol) * 2)
                    = bfpack(e0, e1);
                *(uint32_t*)(fsm + FS_PS_OFF + (size_t)((mrow + 8) * 136 + ncol) * 2)
                    = bfpack(e2, e3);
            }
        }
        __syncthreads();

        // ---- GEMM2 (bf16): feat += Vh @ Psm ----
        const uint32_t aV = aV0 + (uint32_t)buf * FS_VH_BSZ;
#pragma unroll
        for (int kk = 0; kk < 4; kk++) {
            uint32_t A2[4][4];
#pragma unroll
            for (int ct = 0; ct < 4; ct++)
                ldsm_x4(A2[ct], aV + (uint32_t)(ct * 16 * 72) * 2 + kk * 32);
            uint32_t B2[4][2];
#pragma unroll
            for (int nt = 0; nt < 4; nt++)
                ldsm_x2t(B2[nt], bP0 + (uint32_t)(kk * 16 * 136) * 2 + nt * 16);
#pragma unroll
            for (int ct = 0; ct < 4; ct++)
#pragma unroll
                for (int nt = 0; nt < 4; nt++)
                    mma_bf16(acc[ct][nt], A2[ct], B2[nt]);
        }
    }

    zred[t] = zacc;
    __syncthreads();
    for (int s = 128; s > 0; s >>= 1) {
        if (t < s) zred[t] += zred[t + s];
        __syncthreads();
    }
    if (t == 0) g_pZ[b * NT + blockIdx.x] = zred[0];

    float* Ob = out + (size_t)b * (2 * CC) * NPIX + (size_t)CC * NPIX + n0;
#pragma unroll
    for (int ct = 0; ct < 4; ct++) {
        int row = wr * 64 + ct * 16 + g;
#pragma unroll
        for (int nt = 0; nt < 4; nt++) {
            int col = wn * 32 + nt * 8 + 2 * t2;
            *(float2*)&Ob[(size_t)row * NPIX + col] =
                make_float2(acc[ct][nt][0], acc[ct][nt][1]);
            *(float2*)&Ob[(size_t)(row + 8) * NPIX + col] =
                make_float2(acc[ct][nt][2], acc[ct][nt][3]);
        }
    }
}

// ============================================================================
// scale (verbatim)
// ============================================================================
__global__ void __launch_bounds__(256) scale_kernel(float* __restrict__ out)
{
    __shared__ float zinv;
    const int t  = threadIdx.x;
    const int b  = blockIdx.y;
    const int n0 = blockIdx.x * 128;
    if (t == 0) {
        float z = 0.f;
#pragma unroll
        for (int j = 0; j < NT; j++) z += g_pZ[b * NT + j];
        zinv = 1.f / z;
    }
    __syncthreads();
    const float inv = zinv;

    const int c = t >> 1, h = t & 1;
    float* O = out + (size_t)b * (2 * CC) * NPIX + (size_t)(CC + c) * NPIX
                   + n0 + h * 64;
#pragma unroll
    for (int q = 0; q < 16; q++) {
        float4 v = *(float4*)&O[q * 4];
        v.x *= inv; v.y *= inv; v.z *= inv; v.w *= inv;
        *(float4*)&O[q * 4] = v;
    }
}

// ============================================================================
// launch
// ============================================================================
extern "C" void kernel_launch(void* const* d_in, const int* in_sizes, int n_in,
                              void* d_out, int out_size)
{
    const float* x_en   = (const float*)d_in[0];
    const float* x_de   = (const float*)d_in[1];
    const float* x_cat  = (const float*)d_in[2];
    const float* w_kq   = (const float*)d_in[3];
    const float* kq_g   = (const float*)d_in[4];
    const float* kq_b   = (const float*)d_in[5];
    const float* kq_m   = (const float*)d_in[6];
    const float* kq_v   = (const float*)d_in[7];
    const float* w_v    = (const float*)d_in[8];
    const float* v_g    = (const float*)d_in[9];
    const float* v_b    = (const float*)d_in[10];
    const float* v_m    = (const float*)d_in[11];
    const float* v_v    = (const float*)d_in[12];
    const float* w_red  = (const float*)d_in[13];
    const float* red_g  = (const float*)d_in[14];
    const float* red_b  = (const float*)d_in[15];
    const float* red_m  = (const float*)d_in[16];
    const float* red_v  = (const float*)d_in[17];
    float* out = (float*)d_out;

    cudaFuncSetAttribute(convfused_kernel,
                         cudaFuncAttributeMaxDynamicSharedMemorySize, CF_SMEM_BYTES);
    cudaFuncSetAttribute(fused_kernel,
                         cudaFuncAttributeMaxDynamicSharedMemorySize, FS_SMEM_BYTES);

    // Wvh bf16 + Wredt tf32 + zero accums + Xr = rne(x_cat)  (merged)
    prep_kernel<<<2048, 256>>>(w_v, v_g, v_v, w_red, x_cat);
    // Kh bf16 [k][n], QTh bf16 [m][k]
    conv_kq_kernel<<<dim3(NT, BB, 2), 256>>>(x_en, x_de, w_kq,
                                             kq_g, kq_b, kq_m, kq_v);
    // M' partials (per-batch max norms via atomicMax)
    norm_kernel<<<dim3(NT, BB), 128>>>();
    // x (tf32 mma) -> out[0:C) fp32 ; V (bf16 mma) -> g_Vh
    convfused_kernel<<<dim3(NT, BB), 256, CF_SMEM_BYTES>>>(
        red_g, red_b, red_m, red_v,
        v_g, v_b, v_m, v_v, out);
    // fused attention (M' computed in-kernel from g_mk/g_mq)
    fused_kernel<<<dim3(NT, BB), 256, FS_SMEM_BYTES>>>(out);
    // normalize feat half by 1/Z
    scale_kernel<<<dim3(NT, BB), 256>>>(out);
}

// round 17
// speedup vs baseline: 1.4877x; 1.4877x over previous
#include <cuda_runtime.h>
#include <cstdint>

// Problem constants
#define BB   16
#define CC   128
#define C4C  32
#define NPIX 2304                      // H*W = 48*48
#define NT   18                        // NPIX / 128
#define BN_EPS 1e-5f

// -------- scratch (device globals; no allocation allowed) --------
__device__ uint16_t g_Kh   [BB * C4C * NPIX];        // bf16 K [b][k][n]
__device__ uint16_t g_QTh  [BB * NPIX * C4C];        // bf16 QT [b][m][k]
__device__ uint16_t g_Vh   [BB * CC  * NPIX];        // bf16 V [b][c][m]
__device__ uint16_t g_Wvh  [CC * CC];                // bf16 (w_v * bn_scale)
__device__ float    g_Wredt[CC * 2 * CC];            // tf32-RNE w_red
__device__ float    g_Xr   [BB * 2 * CC * NPIX];     // tf32-RNE x_cat (38 MB)
__device__ float    g_pZ   [BB * NT];
__device__ int      g_mk   [BB];                     // atomicMax accum (||K||^2)
__device__ int      g_mq   [BB];                     // atomicMax accum (||Q||^2)

// -------- packed f32x2 helpers --------
__device__ __forceinline__ unsigned long long pk2(float lo, float hi) {
    unsigned long long r;
    asm("mov.b64 %0, {%1,%2};" : "=l"(r) : "f"(lo), "f"(hi));
    return r;
}
__device__ __forceinline__ float2 up2(unsigned long long v) {
    float2 r;
    asm("mov.b64 {%0,%1}, %2;" : "=f"(r.x), "=f"(r.y) : "l"(v));
    return r;
}
__device__ __forceinline__ void fma2(unsigned long long& d,
                                     unsigned long long a,
                                     unsigned long long b) {
    asm("fma.rn.f32x2 %0, %1, %2, %0;" : "+l"(d) : "l"(a), "l"(b));
}
__device__ __forceinline__ uint32_t smem_to_u32(const void* p) {
    uint32_t a;
    asm("{ .reg .u64 t; cvta.to.shared.u64 t, %1; cvt.u32.u64 %0, t; }"
        : "=r"(a) : "l"(p));
    return a;
}
__device__ __forceinline__ void cp16(uint32_t dst, const void* src) {
    asm volatile("cp.async.cg.shared.global [%0], [%1], 16;"
                 :: "r"(dst), "l"(src) : "memory");
}
#define CP_COMMIT() asm volatile("cp.async.commit_group;" ::: "memory")
#define CP_WAIT0()  asm volatile("cp.async.wait_group 0;" ::: "memory")

// pack two f32 -> bf16x2 (lo = p0, hi = p1)
__device__ __forceinline__ uint32_t bfpack(float p0, float p1) {
    uint32_t u;
    asm("cvt.rn.bf16x2.f32 %0, %1, %2;" : "=r"(u) : "f"(p1), "f"(p0));
    return u;
}
__device__ __forceinline__ float bflo(uint32_t u) {
    return __uint_as_float(u << 16);
}
__device__ __forceinline__ float bfhi(uint32_t u) {
    return __uint_as_float(u & 0xFFFF0000u);
}
__device__ __forceinline__ float tf32r(float x) {   // RNE round to tf32
    uint32_t u;
    asm("cvt.rna.tf32.f32 %0, %1;" : "=r"(u) : "f"(x));
    return __uint_as_float(u);
}

// -------- mma.sync + ldmatrix (family-portable, sm_80+) --------
__device__ __forceinline__ void ldsm_x4(uint32_t* r, uint32_t a) {
    asm volatile("ldmatrix.sync.aligned.m8n8.x4.shared.b16 {%0,%1,%2,%3}, [%4];"
        : "=r"(r[0]), "=r"(r[1]), "=r"(r[2]), "=r"(r[3]) : "r"(a));
}
__device__ __forceinline__ void ldsm_x2t(uint32_t* r, uint32_t a) {
    asm volatile("ldmatrix.sync.aligned.m8n8.x2.trans.shared.b16 {%0,%1}, [%2];"
        : "=r"(r[0]), "=r"(r[1]) : "r"(a));
}
__device__ __forceinline__ void mma_bf16(float* d, const uint32_t* a,
                                         const uint32_t* b) {
    asm volatile(
        "mma.sync.aligned.m16n8k16.row.col.f32.bf16.bf16.f32 "
        "{%0,%1,%2,%3},{%4,%5,%6,%7},{%8,%9},{%0,%1,%2,%3};"
        : "+f"(d[0]), "+f"(d[1]), "+f"(d[2]), "+f"(d[3])
        : "r"(a[0]), "r"(a[1]), "r"(a[2]), "r"(a[3]), "r"(b[0]), "r"(b[1]));
}
__device__ __forceinline__ void mma_tf32(float* d, const uint32_t* a,
                                         const uint32_t* b) {
    asm volatile(
        "mma.sync.aligned.m16n8k8.row.col.f32.tf32.tf32.f32 "
        "{%0,%1,%2,%3},{%4,%5,%6,%7},{%8,%9},{%0,%1,%2,%3};"
        : "+f"(d[0]), "+f"(d[1]), "+f"(d[2]), "+f"(d[3])
        : "r"(a[0]), "r"(a[1]), "r"(a[2]), "r"(a[3]), "r"(b[0]), "r"(b[1]));
}

// ============================================================================
// prep (merged): Wvh bf16 + Wredt tf32 RNE + zero norm accums + Xr = rne(x_cat)
// ============================================================================
__global__ void __launch_bounds__(256) prep_kernel(
    const float* __restrict__ Wv,
    const float* __restrict__ v_g, const float* __restrict__ v_v,
    const float* __restrict__ Wred,
    const float* __restrict__ X)
{
    int i = blockIdx.x * 256 + threadIdx.x;
    if (i < BB) { g_mk[i] = 0; g_mq[i] = 0; }
    if (i < CC * CC) {
        int o = i >> 7;
        float s = v_g[o] * rsqrtf(v_v[o] + BN_EPS);
        g_Wvh[i] = (uint16_t)(bfpack(Wv[i] * s, 0.f) & 0xFFFF);
    }
    if (i < CC * 2 * CC) g_Wredt[i] = tf32r(Wred[i]);

    const size_t total4 = (size_t)BB * 2 * CC * NPIX / 4;
    const size_t stride = (size_t)gridDim.x * 256;
    for (size_t j = (size_t)blockIdx.x * 256 + threadIdx.x; j < total4; j += stride) {
        float4 v = ((const float4*)X)[j];
        v.x = tf32r(v.x); v.y = tf32r(v.y);
        v.z = tf32r(v.z); v.w = tf32r(v.w);
        ((float4*)g_Xr)[j] = v;
    }
}

// ============================================================================
// norm (parallel): grid (NT, B), 128 thr; atomicMax partial maxima.
// ============================================================================
__global__ void __launch_bounds__(128) norm_kernel()
{
    __shared__ float r1[128], r2[128];
    const int t  = threadIdx.x;
    const int b  = blockIdx.y;
    const int n  = blockIdx.x * 128 + t;
    const uint16_t* Kb  = g_Kh  + (size_t)b * C4C * NPIX;
    const uint16_t* QTb = g_QTh + (size_t)b * NPIX * C4C;

    float sk = 0.f;
#pragma unroll
    for (int k = 0; k < C4C; k++) {
        float vk = bflo((uint32_t)Kb[(size_t)k * NPIX + n]);
        sk += vk * vk;
    }
    float sq = 0.f;
    const uint32_t* qr = (const uint32_t*)(QTb + (size_t)n * C4C);
#pragma unroll
    for (int j = 0; j < 16; j++) {
        uint32_t u = qr[j];
        float lo = bflo(u), hi = bfhi(u);
        sq += lo * lo + hi * hi;
    }
    r1[t] = sk; r2[t] = sq;
    __syncthreads();
    for (int s = 64; s > 0; s >>= 1) {
        if (t < s) { r1[t] = fmaxf(r1[t], r1[t + s]); r2[t] = fmaxf(r2[t], r2[t + s]); }
        __syncthreads();
    }
    if (t == 0) {
        atomicMax(&g_mk[b], __float_as_int(r1[0]));
        atomicMax(&g_mq[b], __float_as_int(r2[0]));
    }
}

// ============================================================================
// convfused (R12/R15-exact inner loop): phase 1 tf32 mma (pre-rounded);
// phase 2 bf16 mma V-conv.
// ============================================================================
#define CF_XS_OFF   36864
#define CF_WVH_OFF  34816
#define CF_SMEM_BYTES 70656

__global__ void __launch_bounds__(256, 2) convfused_kernel(
    const float* __restrict__ gam, const float* __restrict__ bet,
    const float* __restrict__ mean, const float* __restrict__ var,
    const float* __restrict__ v_g, const float* __restrict__ v_b,
    const float* __restrict__ v_m, const float* __restrict__ v_v,
    float* __restrict__ out)
{
    extern __shared__ __align__(16) char csm[];
    __shared__ float scale_s[128], bias_s[128], biasv_s[128];

    const int t  = threadIdx.x;
    const int b  = blockIdx.y;
    const int n0 = blockIdx.x * 128;
    const int CIN = 2 * CC;
    const int lane = t & 31, wid = t >> 5;
    const int wr = wid >> 2, wn = wid & 3;
    const int g = lane >> 2, t2 = lane & 3;

    if (t < 128) {
        float s = gam[t] * rsqrtf(var[t] + BN_EPS);
        scale_s[t] = s;
        bias_s[t]  = bet[t] - mean[t] * s;
        float sv = v_g[t] * rsqrtf(v_v[t] + BN_EPS);
        biasv_s[t] = v_b[t] - v_m[t] * sv;
    }

    const float* Xb = g_Xr + (size_t)b * CIN * NPIX + n0;
    const uint32_t sb = smem_to_u32(csm);
    float* Wsf = (float*)csm;                       // [2][128][36]
    float* Xsf = (float*)(csm + CF_XS_OFF);         // [2][32][132]

    auto load_chunk = [&](int c0, int buf) {
        {
            int o = t >> 1, h = t & 1;
            uint32_t dst = sb + (uint32_t)(buf * 128 * 36 + o * 36 + h * 16) * 4;
            const float* src = g_Wredt + (size_t)o * CIN + c0 + h * 16;
            cp16(dst, src);      cp16(dst + 16, src + 4);
            cp16(dst + 32, src + 8); cp16(dst + 48, src + 12);
        }
        {
            int k = t >> 3, seg = t & 7;
            uint32_t dst = sb + CF_XS_OFF
                         + (uint32_t)(buf * 32 * 132 + k * 132 + seg * 16) * 4;
            const float* src = Xb + (size_t)(c0 + k) * NPIX + seg * 16;
            cp16(dst, src);      cp16(dst + 16, src + 4);
            cp16(dst + 32, src + 8); cp16(dst + 48, src + 12);
        }
    };

    load_chunk(0, 0);
    CP_COMMIT();

    float acc[4][4][4];
#pragma unroll
    for (int ct = 0; ct < 4; ct++)
#pragma unroll
        for (int nt = 0; nt < 4; nt++)
#pragma unroll
            for (int j = 0; j < 4; j++) acc[ct][nt][j] = 0.f;

    for (int ch = 0; ch < 8; ch++) {
        const int buf = ch & 1;
        CP_WAIT0();
        __syncthreads();
        if (ch + 1 < 8) { load_chunk((ch + 1) << 5, buf ^ 1); CP_COMMIT(); }

        const float* Wb2 = Wsf + buf * 128 * 36;
        const float* Xb2 = Xsf + buf * 32 * 132;
#pragma unroll
        for (int ks = 0; ks < 4; ks++) {
            const int k0 = ks * 8;
            uint32_t A[4][4];
#pragma unroll
            for (int ct = 0; ct < 4; ct++) {
                int r0 = wr * 64 + ct * 16 + g;
                A[ct][0] = __float_as_uint(Wb2[r0 * 36 + k0 + t2]);
                A[ct][1] = __float_as_uint(Wb2[(r0 + 8) * 36 + k0 + t2]);
                A[ct][2] = __float_as_uint(Wb2[r0 * 36 + k0 + 4 + t2]);
                A[ct][3] = __float_as_uint(Wb2[(r0 + 8) * 36 + k0 + 4 + t2]);
            }
            uint32_t Bf[4][2];
#pragma unroll
            for (int nt = 0; nt < 4; nt++) {
                int col = wn * 32 + nt * 8 + g;
                Bf[nt][0] = __float_as_uint(Xb2[(k0 + t2) * 132 + col]);
                Bf[nt][1] = __float_as_uint(Xb2[(k0 + 4 + t2) * 132 + col]);
            }
#pragma unroll
            for (int ct = 0; ct < 4; ct++)
#pragma unroll
                for (int nt = 0; nt < 4; nt++)
                    mma_tf32(acc[ct][nt], A[ct], Bf[nt]);
        }
        __syncthreads();
    }
    __syncthreads();

    {
        int o = t >> 1, h = t & 1;
        uint32_t dst = sb + CF_WVH_OFF + (uint32_t)(o * 136 + h * 64) * 2;
        const uint16_t* src = g_Wvh + (size_t)o * CC + h * 64;
#pragma unroll
        for (int q = 0; q < 8; q++) cp16(dst + q * 16, src + q * 8);
    }
    CP_COMMIT();

    {
        uint16_t* xh = (uint16_t*)csm;              // [128][136]
        float* Yb = out + (size_t)b * (2 * CC) * NPIX + n0;
#pragma unroll
        for (int ct = 0; ct < 4; ct++) {
            int row = wr * 64 + ct * 16 + g;
            float s0 = scale_s[row],     b0 = bias_s[row];
            float s1 = scale_s[row + 8], b1 = bias_s[row + 8];
#pragma unroll
            for (int nt = 0; nt < 4; nt++) {
                int col = wn * 32 + nt * 8 + 2 * t2;
                float r0 = fmaxf(acc[ct][nt][0] * s0 + b0, 0.f);
                float r1 = fmaxf(acc[ct][nt][1] * s0 + b0, 0.f);
                float r2 = fmaxf(acc[ct][nt][2] * s1 + b1, 0.f);
                float r3 = fmaxf(acc[ct][nt][3] * s1 + b1, 0.f);
                *(float2*)&Yb[(size_t)row * NPIX + col]       = make_float2(r0, r1);
                *(float2*)&Yb[(size_t)(row + 8) * NPIX + col] = make_float2(r2, r3);
                *(uint32_t*)&xh[row * 136 + col]       = bfpack(r0, r1);
                *(uint32_t*)&xh[(row + 8) * 136 + col] = bfpack(r2, r3);
            }
        }
    }
    CP_WAIT0();
    __syncthreads();

    const int arow = wr * 64 + ((lane >> 3) & 1) * 8 + (lane & 7);
    const int acol = (lane >> 4) * 8;
    const uint32_t aBase = sb + CF_WVH_OFF + (uint32_t)(arow * 136 + acol) * 2;
    const int l16 = lane & 15;
    const uint32_t bBase = sb + (uint32_t)(l16 * 136 + wn * 32) * 2;

    float vac[4][4][4];
#pragma unroll
    for (int ct = 0; ct < 4; ct++)
#pragma unroll
        for (int nt = 0; nt < 4; nt++)
#pragma unroll
            for (int j = 0; j < 4; j++) vac[ct][nt][j] = 0.f;

#pragma unroll
    for (int kk = 0; kk < 8; kk++) {
        uint32_t A2[4][4];
#pragma unroll
        for (int ct = 0; ct < 4; ct++)
            ldsm_x4(A2[ct], aBase + (uint32_t)(ct * 16 * 136) * 2 + kk * 32);
        uint32_t B2[4][2];
#pragma unroll
        for (int nt = 0; nt < 4; nt++)
            ldsm_x2t(B2[nt], bBase + (uint32_t)(kk * 16 * 136) * 2 + nt * 16);
#pragma unroll
        for (int ct = 0; ct < 4; ct++)
#pragma unroll
            for (int nt = 0; nt < 4; nt++)
                mma_bf16(vac[ct][nt], A2[ct], B2[nt]);
    }

    uint16_t* Vb = g_Vh + (size_t)b * CC * NPIX + n0;
#pragma unroll
    for (int ct = 0; ct < 4; ct++) {
        int row = wr * 64 + ct * 16 + g;
        float b0 = biasv_s[row], b1 = biasv_s[row + 8];
#pragma unroll
        for (int nt = 0; nt < 4; nt++) {
            int col = wn * 32 + nt * 8 + 2 * t2;
            *(uint32_t*)&Vb[(size_t)row * NPIX + col] =
                bfpack(fmaxf(vac[ct][nt][0] + b0, 0.f),
                       fmaxf(vac[ct][nt][1] + b0, 0.f));
            *(uint32_t*)&Vb[(size_t)(row + 8) * NPIX + col] =
                bfpack(fmaxf(vac[ct][nt][2] + b1, 0.f),
                       fmaxf(vac[ct][nt][3] + b1, 0.f));
        }
    }
}

// ============================================================================
// conv_kq (verbatim): z=0 -> Kh bf16 [b][k][n] ; z=1 -> QTh bf16 [b][m][k]
// ============================================================================
__global__ void __launch_bounds__(256, 2) conv_kq_kernel(
    const float* __restrict__ Xen, const float* __restrict__ Xde,
    const float* __restrict__ W,
    const float* __restrict__ gam, const float* __restrict__ bet,
    const float* __restrict__ mean, const float* __restrict__ var)
{
    __shared__ __align__(16) float Ws[2][32 * 20];
    __shared__ __align__(16) float Xs[2][16 * 132];
    __shared__ float scale_s[32], bias_s[32];

    const int t  = threadIdx.x;
    const int b  = blockIdx.y;
    const int n0 = blockIdx.x * 128;
    const int ty = t >> 4, tx = t & 15;
    const float* X = (blockIdx.z == 0) ? Xen : Xde;

    if (t < 32) {
        float s = gam[t] * rsqrtf(var[t] + BN_EPS);
        scale_s[t] = s;
        bias_s[t]  = bet[t] - mean[t] * s;
    }

    const float* Xb = X + (size_t)b * CC * NPIX + n0;
    const uint32_t sW = smem_to_u32(Ws), sX = smem_to_u32(Xs);

    auto load_chunk = [&](int c0, int buf) {
        if (t < 128) {
            int o = t >> 2, q = t & 3;
            cp16(sW + (uint32_t)(buf * 32 * 20 + o * 20 + q * 4) * 4,
                 W + (size_t)o * CC + c0 + q * 4);
        }
        {
            int k = t >> 4, seg = t & 15;
            uint32_t dst = sX + (uint32_t)(buf * 16 * 132 + k * 132 + seg * 8) * 4;
            const float* src = Xb + (size_t)(c0 + k) * NPIX + seg * 8;
            cp16(dst, src); cp16(dst + 16, src + 4);
        }
    };

    load_chunk(0, 0);
    CP_COMMIT();

    unsigned long long acc[2][4];
#pragma unroll
    for (int i = 0; i < 2; i++)
#pragma unroll
        for (int j = 0; j < 4; j++) acc[i][j] = 0ull;

    for (int ch = 0; ch < 8; ch++) {
        const int buf = ch & 1;
        CP_WAIT0();
        __syncthreads();
        if (ch + 1 < 8) { load_chunk((ch + 1) << 4, buf ^ 1); CP_COMMIT(); }

        const float* Wb2 = Ws[buf];
        const float* Xb2 = Xs[buf];
#pragma unroll
        for (int k4 = 0; k4 < 4; k4++) {
            unsigned long long bx[4][4];
#pragma unroll
            for (int kk = 0; kk < 4; kk++)
#pragma unroll
                for (int j = 0; j < 4; j++)
                    bx[kk][j] = *(const unsigned long long*)
                        &Xb2[(k4 * 4 + kk) * 132 + 2 * tx + 32 * j];
#pragma unroll
            for (int i = 0; i < 2; i++) {
                float4 w4 = *(const float4*)&Wb2[(ty * 2 + i) * 20 + k4 * 4];
                unsigned long long d0 = pk2(w4.x, w4.x);
                unsigned long long d1 = pk2(w4.y, w4.y);
                unsigned long long d2 = pk2(w4.z, w4.z);
                unsigned long long d3 = pk2(w4.w, w4.w);
#pragma unroll
                for (int j = 0; j < 4; j++) {
                    fma2(acc[i][j], d0, bx[0][j]);
                    fma2(acc[i][j], d1, bx[1][j]);
                    fma2(acc[i][j], d2, bx[2][j]);
                    fma2(acc[i][j], d3, bx[3][j]);
                }
            }
        }
        __syncthreads();
    }

    if (blockIdx.z == 0) {
        uint16_t* Yb = g_Kh + (size_t)b * C4C * NPIX + n0 + 2 * tx;
#pragma unroll
        for (int i = 0; i < 2; i++) {
            int o = ty * 2 + i;
            float s = scale_s[o], bi = bias_s[o];
#pragma unroll
            for (int j = 0; j < 4; j++) {
                float2 p = up2(acc[i][j]);
                *(uint32_t*)&Yb[(size_t)o * NPIX + 32 * j] =
                    bfpack(fmaxf(p.x * s + bi, 0.f), fmaxf(p.y * s + bi, 0.f));
            }
        }
    } else {
        uint16_t* Yb = g_QTh + (size_t)b * NPIX * C4C;
#pragma unroll
        for (int i = 0; i < 2; i++) {
            int o = ty * 2 + i;
            float s = scale_s[o], bi = bias_s[o];
#pragma unroll
            for (int j = 0; j < 4; j++) {
                float2 p = up2(acc[i][j]);
                int n = n0 + 2 * tx + 32 * j;
                Yb[(size_t)n * C4C + o] =
                    (uint16_t)(bfpack(fmaxf(p.x * s + bi, 0.f), 0.f) & 0xFFFF);
                Yb[(size_t)(n + 1) * C4C + o] =
                    (uint16_t)(bfpack(fmaxf(p.y * s + bi, 0.f), 0.f) & 0xFFFF);
            }
        }
    }
}

// ============================================================================
// fused attention (R15-exact): all-bf16 tensor path, unsplit GEMM1.
// M' computed in-kernel from g_mk/g_mq.
// ============================================================================
#define FS_QT_OFF  8704
#define FS_VH_OFF  18944
#define FS_PS_OFF  55808
#define FS_QT_BSZ  5120
#define FS_VH_BSZ  18432
#define FS_SMEM_BYTES 73216

__global__ void __launch_bounds__(256, 2) fused_kernel(float* __restrict__ out)
{
    extern __shared__ __align__(16) char fsm[];
    __shared__ float zred[256];

    const int t  = threadIdx.x;
    const int b  = blockIdx.y;
    const int n0 = blockIdx.x * 128;
    const int lane = t & 31, wid = t >> 5;
    const int g = lane >> 2, t2 = lane & 3;
    const int wr = wid >> 2, wn = wid & 3;
    const float Mb = sqrtf(__int_as_float(g_mk[b])) * sqrtf(__int_as_float(g_mq[b]));

    const uint32_t sb = smem_to_u32(fsm);
    const uint16_t* Kg  = g_Kh  + (size_t)b * C4C * NPIX + n0;
    const uint16_t* QTg = g_QTh + (size_t)b * NPIX * C4C;
    const uint16_t* Vg  = g_Vh  + (size_t)b * CC * NPIX;

    {
        int k = t >> 3, seg = t & 7;
        uint32_t dst = sb + (uint32_t)(k * 136 + seg * 16) * 2;
        const uint16_t* src = Kg + (size_t)k * NPIX + seg * 16;
        cp16(dst, src); cp16(dst + 16, src + 8);
    }
    auto load_chunk = [&](int m0, int buf) {
        {
            int m = t >> 2, sg = t & 3;
            uint32_t dst = sb + FS_QT_OFF + (uint32_t)buf * FS_QT_BSZ
                         + (uint32_t)(m * 40 + sg * 8) * 2;
            const uint16_t* src = QTg + (size_t)(m0 + m) * C4C + sg * 8;
            cp16(dst, src);
        }
        {
            int c = t >> 1, h = t & 1;
            uint32_t dst = sb + FS_VH_OFF + (uint32_t)buf * FS_VH_BSZ
                         + (uint32_t)(c * 72 + h * 32) * 2;
            const uint16_t* src = Vg + (size_t)c * NPIX + m0 + h * 32;
            cp16(dst, src);      cp16(dst + 16, src + 8);
            cp16(dst + 32, src + 16); cp16(dst + 48, src + 24);
        }
    };
    load_chunk(0, 0);
    CP_COMMIT();

    const int lrow = ((lane >> 3) & 1) * 8 + (lane & 7);
    const int l16  = lane & 15;
    const uint32_t aQ0 = sb + FS_QT_OFF
        + (uint32_t)((wr * 32 + lrow) * 40 + (lane >> 4) * 8) * 2;
    const uint32_t bK0 = sb + (uint32_t)(l16 * 136 + wn * 32) * 2;
    const uint32_t aV0 = sb + FS_VH_OFF
        + (uint32_t)((wr * 64 + lrow) * 72 + (lane >> 4) * 8) * 2;
    const uint32_t bP0 = sb + FS_PS_OFF + (uint32_t)(l16 * 136 + wn * 32) * 2;

    float acc[4][4][4];
#pragma unroll
    for (int ct = 0; ct < 4; ct++)
#pragma unroll
        for (int nt = 0; nt < 4; nt++)
#pragma unroll
            for (int j = 0; j < 4; j++) acc[ct][nt][j] = 0.f;
    float zacc = 0.f;

    for (int ch = 0; ch < 36; ch++) {
        const int buf = ch & 1;
        CP_WAIT0();
        __syncthreads();
        if (ch + 1 < 36) { load_chunk((ch + 1) * 64, buf ^ 1); CP_COMMIT(); }

        float d1[2][4][4];
#pragma unroll
        for (int i = 0; i < 2; i++)
#pragma unroll
            for (int j = 0; j < 4; j++)
#pragma unroll
                for (int q = 0; q < 4; q++) d1[i][j][q] = 0.f;

        const uint32_t aQ = aQ0 + (uint32_t)buf * FS_QT_BSZ;
#pragma unroll
        for (int kk = 0; kk < 2; kk++) {
            uint32_t A[2][4];
#pragma unroll
            for (int m2 = 0; m2 < 2; m2++)
                ldsm_x4(A[m2], aQ + (uint32_t)(m2 * 16 * 40) * 2 + kk * 32);
            uint32_t Bf[4][2];
#pragma unroll
            for (int nt = 0; nt < 4; nt++)
                ldsm_x2t(Bf[nt], bK0 + (uint32_t)(kk * 16 * 136) * 2 + nt * 16);
#pragma unroll
            for (int m2 = 0; m2 < 2; m2++)
#pragma unroll
                for (int nt = 0; nt < 4; nt++)
                    mma_bf16(d1[m2][nt], A[m2], Bf[nt]);
        }

#pragma unroll
        for (int m2 = 0; m2 < 2; m2++) {
            int mrow = wr * 32 + m2 * 16 + g;
#pragma unroll
            for (int nt = 0; nt < 4; nt++) {
                int ncol = wn * 32 + nt * 8 + 2 * t2;
                float e0 = __expf(d1[m2][nt][0] - Mb);
                float e1 = __expf(d1[m2][nt][1] - Mb);
                float e2 = __expf(d1[m2][nt][2] - Mb);
                float e3 = __expf(d1[m2][nt][3] - Mb);
                zacc += (e0 + e1) + (e2 + e3);
                *(uint32_t*)(fsm + FS_PS_OFF + (size_t)(mrow * 136 + ncol) * 2)
                    = bfpack(e0, e1);
                *(uint32_t*)(fsm + FS_PS_OFF + (size_t)((mrow + 8) * 136 + ncol) * 2)
                    = bfpack(e2, e3);
            }
        }
        __syncthreads();

        const uint32_t aV = aV0 + (uint32_t)buf * FS_VH_BSZ;
#pragma unroll
        for (int kk = 0; kk < 4; kk++) {
            uint32_t A2[4][4];
#pragma unroll
            for (int ct = 0; ct < 4; ct++)
                ldsm_x4(A2[ct], aV + (uint32_t)(ct * 16 * 72) * 2 + kk * 32);
            uint32_t B2[4][2];
#pragma unroll
            for (int nt = 0; nt < 4; nt++)
                ldsm_x2t(B2[nt], bP0 + (uint32_t)(kk * 16 * 136) * 2 + nt * 16);
#pragma unroll
            for (int ct = 0; ct < 4; ct++)
#pragma unroll
                for (int nt = 0; nt < 4; nt++)
                    mma_bf16(acc[ct][nt], A2[ct], B2[nt]);
        }
    }

    zred[t] = zacc;
    __syncthreads();
    for (int s = 128; s > 0; s >>= 1) {
        if (t < s) zred[t] += zred[t + s];
        __syncthreads();
    }
    if (t == 0) g_pZ[b * NT + blockIdx.x] = zred[0];

    float* Ob = out + (size_t)b * (2 * CC) * NPIX + (size_t)CC * NPIX + n0;
#pragma unroll
    for (int ct = 0; ct < 4; ct++) {
        int row = wr * 64 + ct * 16 + g;
#pragma unroll
        for (int nt = 0; nt < 4; nt++) {
            int col = wn * 32 + nt * 8 + 2 * t2;
            *(float2*)&Ob[(size_t)row * NPIX + col] =
                make_float2(acc[ct][nt][0], acc[ct][nt][1]);
            *(float2*)&Ob[(size_t)(row + 8) * NPIX + col] =
                make_float2(acc[ct][nt][2], acc[ct][nt][3]);
        }
    }
}

// ============================================================================
// scale (verbatim)
// ============================================================================
__global__ void __launch_bounds__(256) scale_kernel(float* __restrict__ out)
{
    __shared__ float zinv;
    const int t  = threadIdx.x;
    const int b  = blockIdx.y;
    const int n0 = blockIdx.x * 128;
    if (t == 0) {
        float z = 0.f;
#pragma unroll
        for (int j = 0; j < NT; j++) z += g_pZ[b * NT + j];
        zinv = 1.f / z;
    }
    __syncthreads();
    const float inv = zinv;

    const int c = t >> 1, h = t & 1;
    float* O = out + (size_t)b * (2 * CC) * NPIX + (size_t)(CC + c) * NPIX
                   + n0 + h * 64;
#pragma unroll
    for (int q = 0; q < 16; q++) {
        float4 v = *(float4*)&O[q * 4];
        v.x *= inv; v.y *= inv; v.z *= inv; v.w *= inv;
        *(float4*)&O[q * 4] = v;
    }
}

// ============================================================================
// launch
// ============================================================================
extern "C" void kernel_launch(void* const* d_in, const int* in_sizes, int n_in,
                              void* d_out, int out_size)
{
    const float* x_en   = (const float*)d_in[0];
    const float* x_de   = (const float*)d_in[1];
    const float* x_cat  = (const float*)d_in[2];
    const float* w_kq   = (const float*)d_in[3];
    const float* kq_g   = (const float*)d_in[4];
    const float* kq_b   = (const float*)d_in[5];
    const float* kq_m   = (const float*)d_in[6];
    const float* kq_v   = (const float*)d_in[7];
    const float* w_v    = (const float*)d_in[8];
    const float* v_g    = (const float*)d_in[9];
    const float* v_b    = (const float*)d_in[10];
    const float* v_m    = (const float*)d_in[11];
    const float* v_v    = (const float*)d_in[12];
    const float* w_red  = (const float*)d_in[13];
    const float* red_g  = (const float*)d_in[14];
    const float* red_b  = (const float*)d_in[15];
    const float* red_m  = (const float*)d_in[16];
    const float* red_v  = (const float*)d_in[17];
    float* out = (float*)d_out;

    cudaFuncSetAttribute(convfused_kernel,
                         cudaFuncAttributeMaxDynamicSharedMemorySize, CF_SMEM_BYTES);
    cudaFuncSetAttribute(fused_kernel,
                         cudaFuncAttributeMaxDynamicSharedMemorySize, FS_SMEM_BYTES);

    // Wvh bf16 + Wredt tf32 + zero accums + Xr = rne(x_cat)  (merged)
    prep_kernel<<<2048, 256>>>(w_v, v_g, v_v, w_red, x_cat);
    // Kh bf16 [k][n], QTh bf16 [m][k]
    conv_kq_kernel<<<dim3(NT, BB, 2), 256>>>(x_en, x_de, w_kq,
                                             kq_g, kq_b, kq_m, kq_v);
    // M' partials (per-batch max norms via atomicMax)
    norm_kernel<<<dim3(NT, BB), 128>>>();
    // x (tf32 mma) -> out[0:C) fp32 ; V (bf16 mma) -> g_Vh
    convfused_kernel<<<dim3(NT, BB), 256, CF_SMEM_BYTES>>>(
        red_g, red_b, red_m, red_v,
        v_g, v_b, v_m, v_v, out);
    // fused attention (M' in-kernel from g_mk/g_mq)
    fused_kernel<<<dim3(NT, BB), 256, FS_SMEM_BYTES>>>(out);
    // normalize feat half by 1/Z
    scale_kernel<<<dim3(NT, BB), 256>>>(out);
}